// round 14
// baseline (speedup 1.0000x reference)
#include <cuda_runtime.h>

#define B_ 8192
#define T_ 128
#define DT_ 0.01f
#define WARPS 4
#define THREADS 128
#define ROWS_PER_WARP 8
#define NBLK (B_ / (WARPS * ROWS_PER_WARP))   // 256

// shared memory layout (float offsets)
// W1s rows: 0..17 dynamic (e6, ed6, xi6); 18 = beta (xE); 19 = gamma (xnu); 20 = alpha
#define OFF_W1   0        // [21][512]
#define OFF_WEN2 10752    // [256]
#define OFF_WD2T 11008    // [6][256] (transposed Wd2)
#define OFF_XB   12544    // [4 warps][20 k][8 rows x f32x2]  (pre-duplicated inputs)
#define SMEM_FLOATS (12544 + 4 * 320)
#define SMEM_BYTES (SMEM_FLOATS * 4)

typedef unsigned long long u64;

__device__ __forceinline__ u64 ffma2(u64 a, u64 b, u64 c) {
    u64 d; asm("fma.rn.f32x2 %0, %1, %2, %3;" : "=l"(d) : "l"(a), "l"(b), "l"(c));
    return d;
}
__device__ __forceinline__ u64 dup2(float x) {
    u64 d; asm("mov.b64 %0, {%1, %1};" : "=l"(d) : "f"(x));
    return d;
}
__device__ __forceinline__ float2 unpk(u64 a) {
    float2 r; asm("mov.b64 {%0, %1}, %2;" : "=f"(r.x), "=f"(r.y) : "l"(a));
    return r;
}
__device__ __forceinline__ u64 pk2(float x, float y) {
    u64 d; asm("mov.b64 %0, {%1, %2};" : "=l"(d) : "f"(x), "f"(y));
    return d;
}
__device__ __forceinline__ u64 relu2(u64 a) {
    float2 v = unpk(a);
    return pk2(fmaxf(v.x, 0.f), fmaxf(v.y, 0.f));
}

// fold-distribute over 32 slots: lane i ends with full-warp sum of v[i] in v[0]
__device__ __forceinline__ void fold32(float* v, int lane) {
    #pragma unroll
    for (int lvl = 0; lvl < 5; lvl++) {
        const int off = 16 >> lvl;
        #pragma unroll
        for (int m = 0; m < (16 >> lvl); m++) {
            float send = (lane & off) ? v[m] : v[m + off];
            float recv = __shfl_xor_sync(0xffffffffu, send, off);
            float keep = (lane & off) ? v[m + off] : v[m];
            v[m] = keep + recv;
        }
    }
}

__global__ void __launch_bounds__(THREADS, 2) visco_kernel(
    const float* __restrict__ e_,   const float* __restrict__ ed_,
    const float* __restrict__ E_,   const float* __restrict__ nu_,
    const float* __restrict__ We,   const float* __restrict__ be,
    const float* __restrict__ Wn,   const float* __restrict__ bn,
    const float* __restrict__ Wen1, const float* __restrict__ ben1,
    const float* __restrict__ Wen2, const float* __restrict__ ben2,
    const float* __restrict__ Wd1,  const float* __restrict__ bd1,
    const float* __restrict__ Wd2,  const float* __restrict__ bd2,
    float* __restrict__ out)
{
    extern __shared__ float sm[];
    float* W1s   = sm + OFF_W1;
    float* Wen2s = sm + OFF_WEN2;
    float* Wd2t  = sm + OFF_WD2T;

    const int tid  = threadIdx.x;
    const int lane = tid & 31;
    const int warp = tid >> 5;

    float* xbW = sm + OFF_XB + warp * 320;   // [20][16] floats, warp-private

    // ---- cooperative smem fill: dynamic W1 rows 0..17 + layer-2 weights ----
    for (int i = tid; i < 18 * 512; i += THREADS) {
        int k = i >> 9, h = i & 511;
        W1s[i] = (h < 256) ? Wen1[k * 256 + h] : Wd1[k * 256 + (h - 256)];
    }
    for (int i = tid; i < 256; i += THREADS) Wen2s[i] = Wen2[i];
    for (int i = tid; i < 6 * 256; i += THREADS) {
        int j = i >> 8, h = i & 255;
        Wd2t[i] = Wd2[h * 6 + j];   // transpose -> conflict-free float4 reads
    }

    // ---- rows 18..20: beta = We@W1mf, gamma = Wn@W1mf, alpha = bias fold ----
    // mf = [E*We+be, nu*Wn+bn]  =>  c[h] = alpha[h] + E*beta[h] + nu*gamma[h]
    {
        const int h0 = 4 * tid;
        const float* bsrc = (h0 < 256) ? (ben1 + h0) : (bd1 + h0 - 256);
        const float* Wb   = (h0 < 256) ? (Wen1 + 18 * 256 + h0)
                                       : (Wd1  + 18 * 256 + h0 - 256);
        float al[4], bt[4], gm[4];
        #pragma unroll
        for (int el = 0; el < 4; el++) { al[el] = bsrc[el]; bt[el] = 0.f; gm[el] = 0.f; }
        for (int i = 0; i < 16; i++) {
            float4 wa = *(const float4*)(Wb + i * 256);          // W1 row 18+i (E-encoder)
            float4 wb = *(const float4*)(Wb + (16 + i) * 256);   // W1 row 34+i (nu-encoder)
            float wev = We[i], bev = be[i], wnv = Wn[i], bnv = bn[i];
            bt[0] = fmaf(wev, wa.x, bt[0]); bt[1] = fmaf(wev, wa.y, bt[1]);
            bt[2] = fmaf(wev, wa.z, bt[2]); bt[3] = fmaf(wev, wa.w, bt[3]);
            gm[0] = fmaf(wnv, wb.x, gm[0]); gm[1] = fmaf(wnv, wb.y, gm[1]);
            gm[2] = fmaf(wnv, wb.z, gm[2]); gm[3] = fmaf(wnv, wb.w, gm[3]);
            al[0] = fmaf(bev, wa.x, al[0]); al[1] = fmaf(bev, wa.y, al[1]);
            al[2] = fmaf(bev, wa.z, al[2]); al[3] = fmaf(bev, wa.w, al[3]);
            al[0] = fmaf(bnv, wb.x, al[0]); al[1] = fmaf(bnv, wb.y, al[1]);
            al[2] = fmaf(bnv, wb.z, al[2]); al[3] = fmaf(bnv, wb.w, al[3]);
        }
        *(float4*)(W1s + 18 * 512 + h0) = make_float4(bt[0], bt[1], bt[2], bt[3]);
        *(float4*)(W1s + 19 * 512 + h0) = make_float4(gm[0], gm[1], gm[2], gm[3]);
        *(float4*)(W1s + 20 * 512 + h0) = make_float4(al[0], al[1], al[2], al[3]);
    }

    const int gw   = blockIdx.x * WARPS + warp;
    const int row0 = gw * ROWS_PER_WARP;

    // ---- owner mapping: lane < 28: slot = ro*7 + jo serves rows ro (A) and ro+4 (B)
    const int jo = lane % 7;
    const int ro = lane / 7;
    const bool owner = (lane < 28);
    const float bd2v  = (owner && jo < 6) ? bd2[jo] : 0.f;
    const float ben2r = ben2[0];
    float xiv0 = 0.f, xiv1 = 0.f;

    const int rAo = row0 + ((ro < 4) ? ro : 3);       // clamp (lanes>=28 unused)
    float* xiA = out + B_ * T_ + (rAo * T_) * 6 + jo;
    float* xiB = out + B_ * T_ + ((rAo + 4) * T_) * 6 + jo;
    float* sA  = out + rAo * T_;
    float* sB  = out + (rAo + 4) * T_;
    // xi staging slots in the tile (owner lanes, jo<6)
    float* xq0 = xbW + (12 + jo) * 16 + ro * 2;       // row ro
    float* xq1 = xq0 + 8;                              // row ro+4

    // ---- e/edot gather lanes: l2 = k index (0..11), 4 streams of 2 rows each ----
    const int l2  = lane & 15;
    const bool ldp = (l2 < 12);
    const float* lsrc = (l2 < 6) ? e_ : ed_;
    const int d_l = (l2 < 6) ? l2 : (l2 - 6);
    const int rofs = (lane < 16) ? 0 : 1;
    int base[4];
    #pragma unroll
    for (int s = 0; s < 4; s++) base[s] = (row0 + 2 * s + rofs) * T_ * 6 + d_l;
    float* sbase = xbW + l2 * 16 + rofs * 2;          // + s*4

    const float* W1w   = W1s + 4 * lane;            // + k*512 + 128*q
    const float* wen2w = Wen2s + 4 * lane;          // + 128*q
    const float* wd2w  = Wd2t + 4 * lane;           // + j*256 + 128*q

    // ---- initial staging: e/ed(t=0), xi=0, E/nu (static rows 18,19) ----
    if (ldp) {
        #pragma unroll
        for (int s = 0; s < 4; s++) *(u64*)(sbase + s * 4) = dup2(lsrc[base[s]]);
    }
    if (owner && jo < 6) { *(u64*)xq0 = 0ULL; *(u64*)xq1 = 0ULL; }
    if (lane < 8)       *(u64*)(xbW + 18 * 16 + lane * 2)       = dup2(E_[row0 + lane]);
    else if (lane < 16) *(u64*)(xbW + 19 * 16 + (lane - 8) * 2) = dup2(nu_[row0 + lane - 8]);

    __syncthreads();

    // prefetch e/ed for t=1
    float nxt[4] = {0.f, 0.f, 0.f, 0.f};
    if (ldp) {
        #pragma unroll
        for (int s = 0; s < 4; s++) nxt[s] = lsrc[base[s] + 6];
    }

    for (int t = 0; t < T_; t++) {
        __syncwarp();   // order prev-iter xi stores before this step's tile reads

        // prefetch e/ed(t+2) early (hidden under k-loop)
        float pn[4] = {0.f, 0.f, 0.f, 0.f};
        {
            int tn = (t + 2 < T_) ? (t + 2) : (T_ - 1);
            if (ldp) {
                #pragma unroll
                for (int s = 0; s < 4; s++) pn[s] = lsrc[base[s] + tn * 6];
            }
        }

        // ---- init accumulators from shared alpha row (broadcast across rows) ----
        u64 u2[8][4][2];   // [row][q][pair]
        #pragma unroll
        for (int q = 0; q < 4; q++) {
            ulonglong2 a = *(const ulonglong2*)(W1w + 20 * 512 + 128 * q);
            #pragma unroll
            for (int r = 0; r < 8; r++) { u2[r][q][0] = a.x; u2[r][q][1] = a.y; }
        }

        // ---- layer 1: 20 inputs x 512 hidden x 8 rows; inputs via broadcast LDS ----
        #pragma unroll
        for (int k = 0; k < 20; k++) {
            ulonglong2 xa = *(const ulonglong2*)(xbW + k * 16);       // rows 0,1
            ulonglong2 xb = *(const ulonglong2*)(xbW + k * 16 + 4);   // rows 2,3
            ulonglong2 xc = *(const ulonglong2*)(xbW + k * 16 + 8);   // rows 4,5
            ulonglong2 xd2 = *(const ulonglong2*)(xbW + k * 16 + 12); // rows 6,7
            u64 xd[8] = {xa.x, xa.y, xb.x, xb.y, xc.x, xc.y, xd2.x, xd2.y};
            #pragma unroll
            for (int q = 0; q < 4; q++) {
                ulonglong2 w = *(const ulonglong2*)(W1w + k * 512 + 128 * q);
                #pragma unroll
                for (int r = 0; r < 8; r++) {
                    u2[r][q][0] = ffma2(xd[r], w.x, u2[r][q][0]);
                    u2[r][q][1] = ffma2(xd[r], w.y, u2[r][q][1]);
                }
            }
        }

        __syncwarp();   // all lanes done reading e/ed rows before overwrite
        if (ldp) {
            #pragma unroll
            for (int s = 0; s < 4; s++) *(u64*)(sbase + s * 4) = dup2(nxt[s]);
            #pragma unroll
            for (int s = 0; s < 4; s++) nxt[s] = pn[s];
        }

        // relu
        #pragma unroll
        for (int q = 0; q < 4; q++)
            #pragma unroll
            for (int r = 0; r < 8; r++) {
                u2[r][q][0] = relu2(u2[r][q][0]);
                u2[r][q][1] = relu2(u2[r][q][1]);
            }

        // ---- layer-2 partials: tree A (rows 0-3), tree B (rows 4-7); slot = r*7+j ----
        float vA[32], vB[32];
        #pragma unroll
        for (int j = 0; j < 6; j++) {
            ulonglong2 w0 = *(const ulonglong2*)(wd2w + j * 256);
            ulonglong2 w1 = *(const ulonglong2*)(wd2w + j * 256 + 128);
            #pragma unroll
            for (int r = 0; r < 4; r++) {
                u64 a2 = ffma2(u2[r][2][0], w0.x, 0ULL);
                a2 = ffma2(u2[r][2][1], w0.y, a2);
                a2 = ffma2(u2[r][3][0], w1.x, a2);
                a2 = ffma2(u2[r][3][1], w1.y, a2);
                float2 q = unpk(a2);
                vA[r * 7 + j] = q.x + q.y;
            }
            #pragma unroll
            for (int r = 4; r < 8; r++) {
                u64 a2 = ffma2(u2[r][2][0], w0.x, 0ULL);
                a2 = ffma2(u2[r][2][1], w0.y, a2);
                a2 = ffma2(u2[r][3][0], w1.x, a2);
                a2 = ffma2(u2[r][3][1], w1.y, a2);
                float2 q = unpk(a2);
                vB[(r - 4) * 7 + j] = q.x + q.y;
            }
        }
        {
            ulonglong2 w0 = *(const ulonglong2*)(wen2w);
            ulonglong2 w1 = *(const ulonglong2*)(wen2w + 128);
            #pragma unroll
            for (int r = 0; r < 4; r++) {
                u64 s2 = ffma2(u2[r][0][0], w0.x, 0ULL);
                s2 = ffma2(u2[r][0][1], w0.y, s2);
                s2 = ffma2(u2[r][1][0], w1.x, s2);
                s2 = ffma2(u2[r][1][1], w1.y, s2);
                float2 q = unpk(s2);
                vA[r * 7 + 6] = q.x + q.y;
            }
            #pragma unroll
            for (int r = 4; r < 8; r++) {
                u64 s2 = ffma2(u2[r][0][0], w0.x, 0ULL);
                s2 = ffma2(u2[r][0][1], w0.y, s2);
                s2 = ffma2(u2[r][1][0], w1.x, s2);
                s2 = ffma2(u2[r][1][1], w1.y, s2);
                float2 q = unpk(s2);
                vB[(r - 4) * 7 + 6] = q.x + q.y;
            }
        }
        #pragma unroll
        for (int m = 28; m < 32; m++) { vA[m] = 0.f; vB[m] = 0.f; }

        fold32(vA, lane);
        fold32(vB, lane);

        // ---- outputs: xi BEFORE update; stress ----
        if (owner) {
            if (jo < 6) {
                xiA[t * 6] = xiv0;
                xiB[t * 6] = xiv1;
            } else {
                sA[t] = vA[0] + ben2r;
                sB[t] = vB[0] + ben2r;
            }
        }

        // explicit Euler update, then stage xi(t+1) into tile
        xiv0 = fmaf(DT_, vA[0] + bd2v, xiv0);
        xiv1 = fmaf(DT_, vB[0] + bd2v, xiv1);
        if (owner && jo < 6) {
            *(u64*)xq0 = dup2(xiv0);
            *(u64*)xq1 = dup2(xiv1);
        }
    }
}

extern "C" void kernel_launch(void* const* d_in, const int* in_sizes, int n_in,
                              void* d_out, int out_size) {
    (void)in_sizes; (void)n_in; (void)out_size;
    cudaFuncSetAttribute(visco_kernel,
                         cudaFuncAttributeMaxDynamicSharedMemorySize, SMEM_BYTES);
    visco_kernel<<<NBLK, THREADS, SMEM_BYTES>>>(
        (const float*)d_in[0],  (const float*)d_in[1],
        (const float*)d_in[2],  (const float*)d_in[3],
        (const float*)d_in[4],  (const float*)d_in[5],
        (const float*)d_in[6],  (const float*)d_in[7],
        (const float*)d_in[8],  (const float*)d_in[9],
        (const float*)d_in[10], (const float*)d_in[11],
        (const float*)d_in[12], (const float*)d_in[13],
        (const float*)d_in[14], (const float*)d_in[15],
        (float*)d_out);
}